// round 6
// baseline (speedup 1.0000x reference)
#include <cuda_runtime.h>
#include <cstdint>

#define Bn 64
#define Tn 512
#define In 128
#define Hn 512
#define BTH (64*512*512)

// 64MB scratch for precomputed v_in = x @ W_in^T + b_in, layout [B*T, H]
__device__ float g_vin[BTH];

__device__ __forceinline__ uint32_t smem_u32(const void* p) {
    return (uint32_t)__cvta_generic_to_shared(p);
}

// ---------------------------------------------------------------------------
// Kernel 1: v_in GEMM.  out[bt][h] = b_in[h] + sum_i x[bt][i] * W_in[h][i]
// grid (256, 4), block 256. Tile 128(bt) x 128(h), K=128 in one slab.
// ---------------------------------------------------------------------------
#define VIN_SMEM (2*128*132*4)

__global__ __launch_bounds__(256, 1)
void vin_gemm_kernel(const float* __restrict__ x,
                     const float* __restrict__ W_in,
                     const float* __restrict__ b_in) {
    extern __shared__ float sm[];
    float* xs = sm;             // [128 bt][132]   row-major (bt, k)
    float* ws = sm + 128*132;   // [128 k][132]    transposed (k, h)

    const int row0 = blockIdx.x * 128;   // bt tile base
    const int h0   = blockIdx.y * 128;   // h tile base

    for (int idx = threadIdx.x; idx < 128*32; idx += 256) {
        int r = idx >> 5, c4 = idx & 31;
        float4 v = *(const float4*)(x + (size_t)(row0 + r)*In + c4*4);
        *(float4*)(xs + r*132 + c4*4) = v;
        float4 w = *(const float4*)(W_in + (size_t)(h0 + r)*In + c4*4);
        ws[(c4*4 + 0)*132 + r] = w.x;
        ws[(c4*4 + 1)*132 + r] = w.y;
        ws[(c4*4 + 2)*132 + r] = w.z;
        ws[(c4*4 + 3)*132 + r] = w.w;
    }
    __syncthreads();

    const int ty = threadIdx.x >> 4;   // 0..15
    const int tx = threadIdx.x & 15;   // 0..15
    const int rb = ty * 8;
    const int cb = tx * 8;

    float acc[8][8];
    #pragma unroll
    for (int i = 0; i < 8; i++)
        #pragma unroll
        for (int j = 0; j < 8; j++) acc[i][j] = 0.f;

    #pragma unroll 2
    for (int k = 0; k < 128; ++k) {
        float a[8];
        #pragma unroll
        for (int i = 0; i < 8; i++) a[i] = xs[(rb + i)*132 + k];
        float bb[8];
        *(float4*)(bb)     = *(const float4*)(ws + k*132 + cb);
        *(float4*)(bb + 4) = *(const float4*)(ws + k*132 + cb + 4);
        #pragma unroll
        for (int i = 0; i < 8; i++) {
            float av = a[i];
            #pragma unroll
            for (int j = 0; j < 8; j++) acc[i][j] = fmaf(av, bb[j], acc[i][j]);
        }
    }

    float bias[8];
    *(float4*)(bias)     = *(const float4*)(b_in + h0 + cb);
    *(float4*)(bias + 4) = *(const float4*)(b_in + h0 + cb + 4);

    #pragma unroll
    for (int i = 0; i < 8; i++) {
        float* orow = g_vin + (size_t)(row0 + rb + i)*Hn + h0 + cb;
        float4 o0, o1;
        o0.x = acc[i][0] + bias[0]; o0.y = acc[i][1] + bias[1];
        o0.z = acc[i][2] + bias[2]; o0.w = acc[i][3] + bias[3];
        o1.x = acc[i][4] + bias[4]; o1.y = acc[i][5] + bias[5];
        o1.z = acc[i][6] + bias[6]; o1.w = acc[i][7] + bias[7];
        *(float4*)(orow)     = o0;
        *(float4*)(orow + 4) = o1;
    }
}

// ---------------------------------------------------------------------------
// Kernel 2: recurrence. Cluster of 8 CTAs per 4 batches; W_hid slice in smem.
// grid (8, 16), block 256, cluster (8,1,1).
//   smem: Ws[64][516] (129KB) | frs[2][4][512] (16KB) | red[4][4][64] (4KB)
// ---------------------------------------------------------------------------
#define WS_F   (64*516)
#define FRS_F  (2*4*512)
#define RED_F  (4*4*64)
#define REC_SMEM ((WS_F + FRS_F + RED_F)*4)

__global__ __launch_bounds__(256, 1) __cluster_dims__(8, 1, 1)
void recur_kernel(const float* __restrict__ init_state,
                  const float* __restrict__ W_hid,
                  const float* __restrict__ b_hid,
                  const float* __restrict__ alpha,
                  float* __restrict__ out) {
    extern __shared__ float sm[];
    float* Ws  = sm;                 // [64][516] padded, rows = rank's h slice
    float* frs = sm + WS_F;          // [2][4][512] double-buffered fr
    float* red = sm + WS_F + FRS_F;  // [4 seg][4 b][64 h]

    const int tid  = threadIdx.x;
    const int rank = blockIdx.x;     // 0..7 == cluster rank
    const int clu  = blockIdx.y;     // 0..15

    // Load W_hid rows [rank*64, rank*64+64) into padded smem
    for (int idx = tid; idx < 64*128; idx += 256) {
        int hh = idx >> 7, c4 = idx & 127;
        float4 w = *(const float4*)(W_hid + (size_t)(rank*64 + hh)*Hn + c4*4);
        *(float4*)(Ws + hh*516 + c4*4) = w;
    }
    // Init fr = relu(init_state) for this cluster's 4 batches (full 512 vec)
    for (int idx = tid; idx < 512; idx += 256) {
        int b = idx >> 7, c4 = idx & 127;
        float4 s = *(const float4*)(init_state + (size_t)(clu*4 + b)*Hn + c4*4);
        s.x = fmaxf(s.x, 0.f); s.y = fmaxf(s.y, 0.f);
        s.z = fmaxf(s.z, 0.f); s.w = fmaxf(s.w, 0.f);
        *(float4*)(frs + b*512 + c4*4) = s;
    }
    __syncthreads();
    asm volatile("barrier.cluster.arrive.aligned;" ::: "memory");
    asm volatile("barrier.cluster.wait.aligned;"   ::: "memory");

    // roles: j-loop (seg = tid>>6, hlj = tid&63); elementwise (be, he) same split
    const int seg = tid >> 6;
    const int hlj = tid & 63;
    const int be  = tid >> 6;
    const int he  = tid & 63;

    const int bg = clu * 4 + be;         // global batch
    const int hg = rank * 64 + he;       // global h
    const float al   = alpha[hg];
    const float oma  = 1.f - al;
    const float bias = b_hid[hg];
    float v = init_state[(size_t)bg*Hn + hg];

    const float* Wr = Ws + hlj*516 + seg*128;
    const uint32_t frs_u = smem_u32(frs);
    const size_t obase = (size_t)bg * Tn * Hn + hg;

    int cur = 0;
    for (int t = 0; t < Tn; ++t) {
        const size_t ot = obase + (size_t)t * Hn;
        const float vin = __ldg(g_vin + ot);   // issued early, hidden under j-loop

        const float* fb = frs + cur*2048 + seg*128;
        float a0 = 0.f, a1 = 0.f, a2 = 0.f, a3 = 0.f;
        #pragma unroll 4
        for (int jj = 0; jj < 128; jj += 4) {
            float4 w  = *(const float4*)(Wr + jj);
            float4 f0 = *(const float4*)(fb + jj);
            float4 f1 = *(const float4*)(fb + 512  + jj);
            float4 f2 = *(const float4*)(fb + 1024 + jj);
            float4 f3 = *(const float4*)(fb + 1536 + jj);
            a0 = fmaf(w.x, f0.x, fmaf(w.y, f0.y, fmaf(w.z, f0.z, fmaf(w.w, f0.w, a0))));
            a1 = fmaf(w.x, f1.x, fmaf(w.y, f1.y, fmaf(w.z, f1.z, fmaf(w.w, f1.w, a1))));
            a2 = fmaf(w.x, f2.x, fmaf(w.y, f2.y, fmaf(w.z, f2.z, fmaf(w.w, f2.w, a2))));
            a3 = fmaf(w.x, f3.x, fmaf(w.y, f3.y, fmaf(w.z, f3.z, fmaf(w.w, f3.w, a3))));
        }
        red[(seg*4 + 0)*64 + hlj] = a0;
        red[(seg*4 + 1)*64 + hlj] = a1;
        red[(seg*4 + 2)*64 + hlj] = a2;
        red[(seg*4 + 3)*64 + hlj] = a3;
        __syncthreads();

        float vh = red[(0*4 + be)*64 + he] + red[(1*4 + be)*64 + he]
                 + red[(2*4 + be)*64 + he] + red[(3*4 + be)*64 + he] + bias;

        float vn = oma * v + al * (vh + vin);
        float vr = oma * vn + al * vh;
        v = vn;
        float frn = fmaxf(vn, 0.f);
        float frr = fmaxf(vr, 0.f);

        out[ot]       = frn;
        out[BTH + ot] = frr;

        // broadcast fr_new slice into every cluster CTA's next-phase buffer
        const int nxt = cur ^ 1;
        const uint32_t la = frs_u + (uint32_t)(nxt*2048 + be*512 + hg) * 4u;
        #pragma unroll
        for (int rk = 0; rk < 8; rk++) {
            uint32_t ra;
            asm volatile("mapa.shared::cluster.u32 %0, %1, %2;"
                         : "=r"(ra) : "r"(la), "r"(rk));
            asm volatile("st.shared::cluster.f32 [%0], %1;"
                         :: "r"(ra), "f"(frn) : "memory");
        }
        asm volatile("barrier.cluster.arrive.aligned;" ::: "memory");
        asm volatile("barrier.cluster.wait.aligned;"   ::: "memory");
        cur = nxt;
    }
}

// ---------------------------------------------------------------------------
extern "C" void kernel_launch(void* const* d_in, const int* in_sizes, int n_in,
                              void* d_out, int out_size) {
    const float* x          = (const float*)d_in[0];
    const float* init_state = (const float*)d_in[1];
    const float* W_in       = (const float*)d_in[2];
    const float* b_in       = (const float*)d_in[3];
    const float* W_hid      = (const float*)d_in[4];
    const float* b_hid      = (const float*)d_in[5];
    const float* alpha      = (const float*)d_in[6];
    float* out = (float*)d_out;

    cudaFuncSetAttribute(vin_gemm_kernel,
                         cudaFuncAttributeMaxDynamicSharedMemorySize, VIN_SMEM);
    cudaFuncSetAttribute(recur_kernel,
                         cudaFuncAttributeMaxDynamicSharedMemorySize, REC_SMEM);

    vin_gemm_kernel<<<dim3(Bn*Tn/128, Hn/128), 256, VIN_SMEM>>>(x, W_in, b_in);
    recur_kernel<<<dim3(8, Bn/4), 256, REC_SMEM>>>(init_state, W_hid, b_hid, alpha, out);
}

// round 7
// speedup vs baseline: 1.4282x; 1.4282x over previous
#include <cuda_runtime.h>
#include <cstdint>

#define Bn 64
#define Tn 512
#define In 128
#define Hn 512
#define BTH (64*512*512)

// 64MB scratch for precomputed v_in = x @ W_in^T + b_in, layout [B*T, H]
__device__ float g_vin[BTH];

__device__ __forceinline__ uint32_t smem_u32(const void* p) {
    return (uint32_t)__cvta_generic_to_shared(p);
}

// Packed fp32x2 FMA (Blackwell FFMA2): d = a*b + d on both lanes, exact fp32.
__device__ __forceinline__ void ffma2(unsigned long long& d,
                                      unsigned long long a,
                                      unsigned long long b) {
    asm("fma.rn.f32x2 %0, %1, %2, %0;" : "+l"(d) : "l"(a), "l"(b));
}
__device__ __forceinline__ float hsum2(unsigned long long a) {
    float lo, hi;
    asm("mov.b64 {%0, %1}, %2;" : "=f"(lo), "=f"(hi) : "l"(a));
    return lo + hi;
}

// ---------------------------------------------------------------------------
// Kernel 1: v_in GEMM.  g_vin[bt][h] = b_in[h] + sum_i x[bt][i] * W_in[h][i]
// ---------------------------------------------------------------------------
#define VIN_SMEM (2*128*132*4)

__global__ __launch_bounds__(256, 1)
void vin_gemm_kernel(const float* __restrict__ x,
                     const float* __restrict__ W_in,
                     const float* __restrict__ b_in) {
    extern __shared__ float sm[];
    float* xs = sm;             // [128 bt][132]
    float* ws = sm + 128*132;   // [128 k][132]

    const int row0 = blockIdx.x * 128;
    const int h0   = blockIdx.y * 128;

    for (int idx = threadIdx.x; idx < 128*32; idx += 256) {
        int r = idx >> 5, c4 = idx & 31;
        float4 v = *(const float4*)(x + (size_t)(row0 + r)*In + c4*4);
        *(float4*)(xs + r*132 + c4*4) = v;
        float4 w = *(const float4*)(W_in + (size_t)(h0 + r)*In + c4*4);
        ws[(c4*4 + 0)*132 + r] = w.x;
        ws[(c4*4 + 1)*132 + r] = w.y;
        ws[(c4*4 + 2)*132 + r] = w.z;
        ws[(c4*4 + 3)*132 + r] = w.w;
    }
    __syncthreads();

    const int ty = threadIdx.x >> 4;
    const int tx = threadIdx.x & 15;
    const int rb = ty * 8;
    const int cb = tx * 8;

    float acc[8][8];
    #pragma unroll
    for (int i = 0; i < 8; i++)
        #pragma unroll
        for (int j = 0; j < 8; j++) acc[i][j] = 0.f;

    #pragma unroll 2
    for (int k = 0; k < 128; ++k) {
        float a[8];
        #pragma unroll
        for (int i = 0; i < 8; i++) a[i] = xs[(rb + i)*132 + k];
        float bb[8];
        *(float4*)(bb)     = *(const float4*)(ws + k*132 + cb);
        *(float4*)(bb + 4) = *(const float4*)(ws + k*132 + cb + 4);
        #pragma unroll
        for (int i = 0; i < 8; i++) {
            float av = a[i];
            #pragma unroll
            for (int j = 0; j < 8; j++) acc[i][j] = fmaf(av, bb[j], acc[i][j]);
        }
    }

    float bias[8];
    *(float4*)(bias)     = *(const float4*)(b_in + h0 + cb);
    *(float4*)(bias + 4) = *(const float4*)(b_in + h0 + cb + 4);

    #pragma unroll
    for (int i = 0; i < 8; i++) {
        float* orow = g_vin + (size_t)(row0 + rb + i)*Hn + h0 + cb;
        float4 o0, o1;
        o0.x = acc[i][0] + bias[0]; o0.y = acc[i][1] + bias[1];
        o0.z = acc[i][2] + bias[2]; o0.w = acc[i][3] + bias[3];
        o1.x = acc[i][4] + bias[4]; o1.y = acc[i][5] + bias[5];
        o1.z = acc[i][6] + bias[6]; o1.w = acc[i][7] + bias[7];
        *(float4*)(orow)     = o0;
        *(float4*)(orow + 4) = o1;
    }
}

// ---------------------------------------------------------------------------
// Kernel 2: recurrence. 16 clusters x 8 CTAs; 4 batches per cluster.
// 512 threads/CTA. Thread (seg=tid>>6, hlj=tid&63) holds W_hid row
// (rank*64+hlj), cols [seg*64, seg*64+64) IN REGISTERS as 32 f32x2 pairs.
// Per step: 128 FFMA2 + 64 broadcast LDS.128 per thread; stride-5 padded
// smem reduction over 8 segments; elementwise update on threads < 256;
// fr fan-out via st.shared::cluster; split cluster barrier hides STG+prefetch.
//   smem: frs[2][4][512] (16KB) | red[8][64][5] (10KB)
// ---------------------------------------------------------------------------
#define FRS_F  (2*4*512)
#define RED_F  (8*64*5)
#define REC_SMEM ((FRS_F + RED_F)*4)

__global__ __launch_bounds__(512, 1) __cluster_dims__(8, 1, 1)
void recur_kernel(const float* __restrict__ init_state,
                  const float* __restrict__ W_hid,
                  const float* __restrict__ b_hid,
                  const float* __restrict__ alpha,
                  float* __restrict__ out) {
    extern __shared__ float sm[];
    float* frs = sm;           // [2][4][512] double-buffered fr
    float* red = sm + FRS_F;   // [8 seg][64 h][5] (stride-5 pad: conflict-free)

    const int tid  = threadIdx.x;
    const int rank = blockIdx.x;     // cluster rank 0..7 -> h slice
    const int clu  = blockIdx.y;     // 0..15 -> 4-batch group
    const int seg  = tid >> 6;       // 0..7 (64-wide j segment)
    const int hlj  = tid & 63;       // h within CTA slice

    // ---- W_hid slice into registers: 16 x ulonglong2 = 32 f32x2 pairs ----
    ulonglong2 w[16];
    {
        const float* wr = W_hid + (size_t)(rank*64 + hlj)*Hn + seg*64;
        #pragma unroll
        for (int i = 0; i < 16; i++)
            w[i] = *(const ulonglong2*)(wr + i*4);
    }

    // ---- init frs[0] = relu(init_state) for this cluster's 4 batches ----
    {
        int b = tid >> 7, c4 = tid & 127;
        float4 s = *(const float4*)(init_state + (size_t)(clu*4 + b)*Hn + c4*4);
        s.x = fmaxf(s.x, 0.f); s.y = fmaxf(s.y, 0.f);
        s.z = fmaxf(s.z, 0.f); s.w = fmaxf(s.w, 0.f);
        *(float4*)(frs + b*512 + c4*4) = s;
    }

    // ---- elementwise role state (threads < 256): (be, he) = (b, h) ----
    const bool ew = (tid < 256);
    const int  be = tid >> 6;                 // 0..3 (when ew)
    const int  he = tid & 63;
    const int  bg = clu * 4 + be;
    const int  hg = rank * 64 + he;
    float al = 0.f, oma = 0.f, bias = 0.f, v = 0.f, vin = 0.f;
    size_t obase = 0;
    if (ew) {
        al   = alpha[hg];
        oma  = 1.f - al;
        bias = b_hid[hg];
        v    = init_state[(size_t)bg*Hn + hg];
        obase = (size_t)bg * Tn * Hn + hg;
        vin  = __ldg(g_vin + obase);          // t = 0
    }
    const uint32_t frs_u = smem_u32(frs);

    __syncthreads();
    asm volatile("barrier.cluster.arrive.aligned;" ::: "memory");
    asm volatile("barrier.cluster.wait.aligned;"   ::: "memory");

    int cur = 0;
    for (int t = 0; t < Tn; ++t) {
        // ---- j-loop: 4-batch dot over this thread's 64-j segment ----
        const float* fb = frs + cur*2048 + seg*64;
        unsigned long long a0 = 0ull, a1 = 0ull, a2 = 0ull, a3 = 0ull;
        #pragma unroll
        for (int i = 0; i < 16; i++) {
            ulonglong2 f0 = *(const ulonglong2*)(fb + i*4);
            ulonglong2 f1 = *(const ulonglong2*)(fb + 512  + i*4);
            ulonglong2 f2 = *(const ulonglong2*)(fb + 1024 + i*4);
            ulonglong2 f3 = *(const ulonglong2*)(fb + 1536 + i*4);
            ffma2(a0, w[i].x, f0.x); ffma2(a0, w[i].y, f0.y);
            ffma2(a1, w[i].x, f1.x); ffma2(a1, w[i].y, f1.y);
            ffma2(a2, w[i].x, f2.x); ffma2(a2, w[i].y, f2.y);
            ffma2(a3, w[i].x, f3.x); ffma2(a3, w[i].y, f3.y);
        }
        {
            float* rr = red + (seg*64 + hlj)*5;
            rr[0] = hsum2(a0); rr[1] = hsum2(a1);
            rr[2] = hsum2(a2); rr[3] = hsum2(a3);
        }
        __syncthreads();

        float frn = 0.f, frr = 0.f;
        size_t ot = 0;
        if (ew) {
            float vh = bias;
            #pragma unroll
            for (int s = 0; s < 8; s++)
                vh += red[(s*64 + he)*5 + be];

            float vn = oma * v + al * (vh + vin);
            float vr = oma * vn + al * vh;
            v = vn;
            frn = fmaxf(vn, 0.f);
            frr = fmaxf(vr, 0.f);

            // fan out fr_new[bg][hg] into every cluster CTA's next buffer
            const uint32_t la = frs_u +
                (uint32_t)(((cur ^ 1)*2048 + be*512 + hg) * 4);
            #pragma unroll
            for (int rk = 0; rk < 8; rk++) {
                uint32_t ra;
                asm volatile("mapa.shared::cluster.u32 %0, %1, %2;"
                             : "=r"(ra) : "r"(la), "r"(rk));
                asm volatile("st.shared::cluster.f32 [%0], %1;"
                             :: "r"(ra), "f"(frn) : "memory");
            }
            ot = obase + (size_t)t * Hn;
        }

        // split barrier: arrive (release of the remote stores), then hide
        // the output stores + next v_in load inside the wait.
        asm volatile("barrier.cluster.arrive.aligned;" ::: "memory");
        if (ew) {
            out[ot]       = frn;
            out[BTH + ot] = frr;
            if (t + 1 < Tn) vin = __ldg(g_vin + ot + Hn);
        }
        asm volatile("barrier.cluster.wait.aligned;"   ::: "memory");
        cur ^= 1;
    }
}

// ---------------------------------------------------------------------------
extern "C" void kernel_launch(void* const* d_in, const int* in_sizes, int n_in,
                              void* d_out, int out_size) {
    const float* x          = (const float*)d_in[0];
    const float* init_state = (const float*)d_in[1];
    const float* W_in       = (const float*)d_in[2];
    const float* b_in       = (const float*)d_in[3];
    const float* W_hid      = (const float*)d_in[4];
    const float* b_hid      = (const float*)d_in[5];
    const float* alpha      = (const float*)d_in[6];
    float* out = (float*)d_out;

    cudaFuncSetAttribute(vin_gemm_kernel,
                         cudaFuncAttributeMaxDynamicSharedMemorySize, VIN_SMEM);

    vin_gemm_kernel<<<dim3(Bn*Tn/128, Hn/128), 256, VIN_SMEM>>>(x, W_in, b_in);
    recur_kernel<<<dim3(8, Bn/4), 512, REC_SMEM>>>(init_state, W_hid, b_hid,
                                                   alpha, out);
}

// round 10
// speedup vs baseline: 1.7866x; 1.2509x over previous
#include <cuda_runtime.h>
#include <cstdint>

#define Bn 64
#define Tn 512
#define In 128
#define Hn 512
#define BTH (64*512*512)

// 64MB scratch for precomputed v_in = x @ W_in^T + b_in, layout [B*T, H]
__device__ float g_vin[BTH];

__device__ __forceinline__ uint32_t smem_u32(const void* p) {
    return (uint32_t)__cvta_generic_to_shared(p);
}

// Packed fp32x2 FMA (Blackwell FFMA2): d = a*b + d on both lanes, exact fp32.
__device__ __forceinline__ void ffma2(unsigned long long& d,
                                      unsigned long long a,
                                      unsigned long long b) {
    asm("fma.rn.f32x2 %0, %1, %2, %0;" : "+l"(d) : "l"(a), "l"(b));
}
__device__ __forceinline__ float hsum2(unsigned long long a) {
    float lo, hi;
    asm("mov.b64 {%0, %1}, %2;" : "=f"(lo), "=f"(hi) : "l"(a));
    return lo + hi;
}

__device__ __forceinline__ void mbar_init(uint32_t mbar, uint32_t cnt) {
    asm volatile("mbarrier.init.shared.b64 [%0], %1;" :: "r"(mbar), "r"(cnt) : "memory");
}
__device__ __forceinline__ void mbar_expect_tx(uint32_t mbar, uint32_t bytes) {
    asm volatile("mbarrier.arrive.expect_tx.shared.b64 _, [%0], %1;"
                 :: "r"(mbar), "r"(bytes) : "memory");
}
__device__ __forceinline__ void mbar_wait(uint32_t mbar, uint32_t parity) {
    asm volatile(
        "{\n\t.reg .pred P;\n\t"
        "WL_%=:\n\t"
        "mbarrier.try_wait.parity.acquire.cta.shared::cta.b64 P, [%0], %1, 0x989680;\n\t"
        "@!P bra WL_%=;\n\t}"
        :: "r"(mbar), "r"(parity) : "memory");
}
__device__ __forceinline__ uint32_t mapa_rk(uint32_t la, int rk) {
    uint32_t ra;
    asm("mapa.shared::cluster.u32 %0, %1, %2;" : "=r"(ra) : "r"(la), "r"(rk));
    return ra;
}
// Remote smem store that also delivers complete_tx to the remote mbarrier.
__device__ __forceinline__ void st_async_f32(uint32_t raddr, float v, uint32_t rmbar) {
    asm volatile("st.async.shared::cluster.mbarrier::complete_tx::bytes.f32 [%0], %1, [%2];"
                 :: "r"(raddr), "f"(v), "r"(rmbar) : "memory");
}

// ---------------------------------------------------------------------------
// Kernel 1: v_in GEMM.  g_vin[bt][h] = b_in[h] + sum_i x[bt][i] * W_in[h][i]
// ---------------------------------------------------------------------------
#define VIN_SMEM (2*128*132*4)

__global__ __launch_bounds__(256, 1)
void vin_gemm_kernel(const float* __restrict__ x,
                     const float* __restrict__ W_in,
                     const float* __restrict__ b_in) {
    extern __shared__ float sm[];
    float* xs = sm;             // [128 bt][132]
    float* ws = sm + 128*132;   // [128 k][132]

    const int row0 = blockIdx.x * 128;
    const int h0   = blockIdx.y * 128;

    for (int idx = threadIdx.x; idx < 128*32; idx += 256) {
        int r = idx >> 5, c4 = idx & 31;
        float4 v = *(const float4*)(x + (size_t)(row0 + r)*In + c4*4);
        *(float4*)(xs + r*132 + c4*4) = v;
        float4 w = *(const float4*)(W_in + (size_t)(h0 + r)*In + c4*4);
        ws[(c4*4 + 0)*132 + r] = w.x;
        ws[(c4*4 + 1)*132 + r] = w.y;
        ws[(c4*4 + 2)*132 + r] = w.z;
        ws[(c4*4 + 3)*132 + r] = w.w;
    }
    __syncthreads();

    const int ty = threadIdx.x >> 4;
    const int tx = threadIdx.x & 15;
    const int rb = ty * 8;
    const int cb = tx * 8;

    float acc[8][8];
    #pragma unroll
    for (int i = 0; i < 8; i++)
        #pragma unroll
        for (int j = 0; j < 8; j++) acc[i][j] = 0.f;

    #pragma unroll 2
    for (int k = 0; k < 128; ++k) {
        float a[8];
        #pragma unroll
        for (int i = 0; i < 8; i++) a[i] = xs[(rb + i)*132 + k];
        float bb[8];
        *(float4*)(bb)     = *(const float4*)(ws + k*132 + cb);
        *(float4*)(bb + 4) = *(const float4*)(ws + k*132 + cb + 4);
        #pragma unroll
        for (int i = 0; i < 8; i++) {
            float av = a[i];
            #pragma unroll
            for (int j = 0; j < 8; j++) acc[i][j] = fmaf(av, bb[j], acc[i][j]);
        }
    }

    float bias[8];
    *(float4*)(bias)     = *(const float4*)(b_in + h0 + cb);
    *(float4*)(bias + 4) = *(const float4*)(b_in + h0 + cb + 4);

    #pragma unroll
    for (int i = 0; i < 8; i++) {
        float* orow = g_vin + (size_t)(row0 + rb + i)*Hn + h0 + cb;
        float4 o0, o1;
        o0.x = acc[i][0] + bias[0]; o0.y = acc[i][1] + bias[1];
        o0.z = acc[i][2] + bias[2]; o0.w = acc[i][3] + bias[3];
        o1.x = acc[i][4] + bias[4]; o1.y = acc[i][5] + bias[5];
        o1.z = acc[i][6] + bias[6]; o1.w = acc[i][7] + bias[7];
        *(float4*)(orow)     = o0;
        *(float4*)(orow + 4) = o1;
    }
}

// ---------------------------------------------------------------------------
// Kernel 2: recurrence, ping-pong two batch groups per cluster.
// 16 clusters x 8 CTAs, 512 thr. Group A = batches {0,1}, B = {2,3}.
// W_hid slice in registers (64 f32/thread). Per half-step:
//   mbar wait (acquire) -> expect_tx re-arm -> j-loop (64 FFMA2/thread)
//   -> padded smem reduce -> 128 ew threads: update + 8x st.async fan-out
//   (data + complete_tx in one instr, SKIPPED on final step) + STG + prefetch.
// Group B's half-step hides group A's store/arrival latency and vice versa.
// Trailing cluster barrier prevents smem-deallocation-vs-inflight-store race.
//   smem: frA[2][2][512] frB[2][2][512] redA[8*64*5] redB[8*64*5] mbars[4]
// ---------------------------------------------------------------------------
#define FRG_F  (2*2*512)
#define RED_F  (8*64*5)
#define MB_OFF ((2*FRG_F + 2*RED_F)*4)
#define REC_SMEM (MB_OFF + 64)
#define TX_BYTES 4096u   // per dest per phase: 2 batches x 512 h x 4B

struct EwState { float al, oma, bias, v, vin; size_t obase; };

template<bool DOWAIT, bool DOSIG, int RB, int WB>
__device__ __forceinline__ void half_step(
    float* __restrict__ fr, uint32_t fr_u, float* __restrict__ red,
    uint32_t mb_wait, const uint32_t* mb_sig_r, int parity,
    const ulonglong2* w, int seg, int hlj,
    bool ewp, int be, int hg, EwState& S,
    float* __restrict__ out, int t)
{
    if (DOWAIT) {
        mbar_wait(mb_wait, (uint32_t)parity);
        if (threadIdx.x == 0) mbar_expect_tx(mb_wait, TX_BYTES);  // re-arm next phase
    }

    // j-loop: this thread's 64-j segment vs both batches of the group
    const float* fb = fr + RB*1024 + seg*64;
    unsigned long long a0e = 0ull, a0o = 0ull, a1e = 0ull, a1o = 0ull;
    #pragma unroll
    for (int i = 0; i < 16; i++) {
        ulonglong2 f0 = *(const ulonglong2*)(fb + i*4);
        ulonglong2 f1 = *(const ulonglong2*)(fb + 512 + i*4);
        ffma2(a0e, w[i].x, f0.x); ffma2(a0o, w[i].y, f0.y);
        ffma2(a1e, w[i].x, f1.x); ffma2(a1o, w[i].y, f1.y);
    }
    {
        float* rr = red + (seg*64 + hlj)*5;
        rr[0] = hsum2(a0e) + hsum2(a0o);
        rr[1] = hsum2(a1e) + hsum2(a1o);
    }
    __syncthreads();

    if (ewp) {
        const int he = hg & 63;
        float vh = S.bias;
        #pragma unroll
        for (int s = 0; s < 8; s++) vh += red[(s*64 + he)*5 + be];

        float vn = S.oma * S.v + S.al * (vh + S.vin);
        float vr = S.oma * vn + S.al * vh;
        S.v = vn;
        float frn = fmaxf(vn, 0.f);
        float frr = fmaxf(vr, 0.f);

        // fan out fr_new to all 8 CTAs' write buffer + signal their mbar.
        // Skipped on the final step (nobody consumes it; also avoids any
        // in-flight remote store outliving a peer CTA).
        if (DOSIG) {
            const uint32_t la = fr_u + (uint32_t)((WB*2 + be)*512 + hg) * 4u;
            #pragma unroll
            for (int rk = 0; rk < 8; rk++)
                st_async_f32(mapa_rk(la, rk), frn, mb_sig_r[rk]);
        }

        const size_t ot = S.obase + (size_t)t * Hn;
        out[ot]       = frn;
        out[BTH + ot] = frr;
        if (t + 1 < Tn) S.vin = __ldg(g_vin + ot + Hn);
    }
}

__global__ __launch_bounds__(512, 1) __cluster_dims__(8, 1, 1)
void recur_kernel(const float* __restrict__ init_state,
                  const float* __restrict__ W_hid,
                  const float* __restrict__ b_hid,
                  const float* __restrict__ alpha,
                  float* __restrict__ out) {
    extern __shared__ float sm[];
    float* frA  = sm;                       // [2 buf][2 batch][512]
    float* frB  = sm + FRG_F;
    float* redA = sm + 2*FRG_F;             // [8 seg][64 h][5]
    float* redB = sm + 2*FRG_F + RED_F;

    const int tid  = threadIdx.x;
    const int rank = blockIdx.x;            // cluster rank -> h slice
    const int clu  = blockIdx.y;
    const int seg  = tid >> 6;
    const int hlj  = tid & 63;

    const uint32_t smb   = smem_u32(sm);
    const uint32_t frA_u = smb;
    const uint32_t frB_u = smb + FRG_F*4;
    const uint32_t mbA0  = smb + MB_OFF;
    const uint32_t mbA1  = mbA0 + 8;
    const uint32_t mbB0  = mbA0 + 16;
    const uint32_t mbB1  = mbA0 + 24;

    // ---- W_hid slice into registers (row rank*64+hlj, cols seg*64..+64) ----
    ulonglong2 w[16];
    {
        const float* wr = W_hid + (size_t)(rank*64 + hlj)*Hn + seg*64;
        #pragma unroll
        for (int i = 0; i < 16; i++)
            w[i] = *(const ulonglong2*)(wr + i*4);
    }

    // ---- init fr buffers (buf 0) with relu(init_state) ----
    {
        int b4 = tid >> 7, c4 = tid & 127;   // batch-in-cluster 0..3
        float4 s = *(const float4*)(init_state + (size_t)(clu*4 + b4)*Hn + c4*4);
        s.x = fmaxf(s.x, 0.f); s.y = fmaxf(s.y, 0.f);
        s.z = fmaxf(s.z, 0.f); s.w = fmaxf(s.w, 0.f);
        float* dst = (b4 < 2) ? (frA + b4*512) : (frB + (b4 - 2)*512);
        *(float4*)(dst + c4*4) = s;
    }

    // ---- mbarrier init + prologue arm ----
    if (tid == 0) {
        mbar_init(mbA0, 1); mbar_init(mbA1, 1);
        mbar_init(mbB0, 1); mbar_init(mbB1, 1);
        asm volatile("fence.mbarrier_init.release.cluster;" ::: "memory");
        mbar_expect_tx(mbA0, TX_BYTES); mbar_expect_tx(mbA1, TX_BYTES);
        mbar_expect_tx(mbB0, TX_BYTES); mbar_expect_tx(mbB1, TX_BYTES);
    }

    // ---- elementwise role: tid<128 -> group A, 128..255 -> group B ----
    const bool ewA = (tid < 128);
    const bool ewB = (tid >= 128) && (tid < 256);
    const int  be  = (tid >> 6) & 1;
    const int  grp = (tid >> 7) & 1;
    const int  hg  = rank*64 + (tid & 63);
    const int  bg  = clu*4 + grp*2 + be;
    EwState S;
    if (tid < 256) {
        S.al    = alpha[hg];
        S.oma   = 1.f - S.al;
        S.bias  = b_hid[hg];
        S.v     = init_state[(size_t)bg*Hn + hg];
        S.obase = (size_t)bg * Tn * Hn + hg;
        S.vin   = __ldg(g_vin + S.obase);
    }

    // Precompute remote mbar addresses (loop-invariant) for the signal path.
    // sig0[rk]: this group's slot-0 mbar in rank rk; sig1: slot-1 mbar.
    uint32_t sigA0[8], sigA1[8], sigB0[8], sigB1[8];
    #pragma unroll
    for (int rk = 0; rk < 8; rk++) {
        sigA0[rk] = mapa_rk(mbA0, rk);
        sigA1[rk] = mapa_rk(mbA1, rk);
        sigB0[rk] = mapa_rk(mbB0, rk);
        sigB1[rk] = mapa_rk(mbB1, rk);
    }

    __syncthreads();
    asm volatile("barrier.cluster.arrive.aligned;" ::: "memory");
    asm volatile("barrier.cluster.wait.aligned;"   ::: "memory");

    // ---- peeled u = 0: t=0 (no wait, read buf0, signal slot1 mbars),
    //                    t=1 (wait slot1 parity0, read buf1, signal slot0) ----
    half_step<false,true,0,1>(frA, frA_u, redA, mbA0, sigA1, 0, w, seg, hlj, ewA, be, hg, S, out, 0);
    half_step<false,true,0,1>(frB, frB_u, redB, mbB0, sigB1, 0, w, seg, hlj, ewB, be, hg, S, out, 0);
    half_step<true, true,1,0>(frA, frA_u, redA, mbA1, sigA0, 0, w, seg, hlj, ewA, be, hg, S, out, 1);
    half_step<true, true,1,0>(frB, frB_u, redB, mbB1, sigB0, 0, w, seg, hlj, ewB, be, hg, S, out, 1);

    #pragma unroll 1
    for (int u = 1; u < Tn/2 - 1; ++u) {
        const int p1 = u & 1;        // slot1 parity
        const int p0 = p1 ^ 1;       // slot0 parity
        const int t0 = 2*u, t1 = 2*u + 1;
        half_step<true,true,0,1>(frA, frA_u, redA, mbA0, sigA1, p0, w, seg, hlj, ewA, be, hg, S, out, t0);
        half_step<true,true,0,1>(frB, frB_u, redB, mbB0, sigB1, p0, w, seg, hlj, ewB, be, hg, S, out, t0);
        half_step<true,true,1,0>(frA, frA_u, redA, mbA1, sigA0, p1, w, seg, hlj, ewA, be, hg, S, out, t1);
        half_step<true,true,1,0>(frB, frB_u, redB, mbB1, sigB0, p1, w, seg, hlj, ewB, be, hg, S, out, t1);
    }

    // ---- final u = Tn/2 - 1 = 255: last half-step pair skips the fan-out ----
    {
        const int u  = Tn/2 - 1;
        const int p1 = u & 1;
        const int p0 = p1 ^ 1;
        const int t0 = 2*u, t1 = 2*u + 1;
        half_step<true,true, 0,1>(frA, frA_u, redA, mbA0, sigA1, p0, w, seg, hlj, ewA, be, hg, S, out, t0);
        half_step<true,true, 0,1>(frB, frB_u, redB, mbB0, sigB1, p0, w, seg, hlj, ewB, be, hg, S, out, t0);
        half_step<true,false,1,0>(frA, frA_u, redA, mbA1, sigA0, p1, w, seg, hlj, ewA, be, hg, S, out, t1);
        half_step<true,false,1,0>(frB, frB_u, redB, mbB1, sigB0, p1, w, seg, hlj, ewB, be, hg, S, out, t1);
    }

    // No CTA may exit while a peer could still have remote stores in flight
    // toward its smem (exit deallocates smem -> fault).
    asm volatile("barrier.cluster.arrive.aligned;" ::: "memory");
    asm volatile("barrier.cluster.wait.aligned;"   ::: "memory");
}

// ---------------------------------------------------------------------------
extern "C" void kernel_launch(void* const* d_in, const int* in_sizes, int n_in,
                              void* d_out, int out_size) {
    const float* x          = (const float*)d_in[0];
    const float* init_state = (const float*)d_in[1];
    const float* W_in       = (const float*)d_in[2];
    const float* b_in       = (const float*)d_in[3];
    const float* W_hid      = (const float*)d_in[4];
    const float* b_hid      = (const float*)d_in[5];
    const float* alpha      = (const float*)d_in[6];
    float* out = (float*)d_out;

    cudaFuncSetAttribute(vin_gemm_kernel,
                         cudaFuncAttributeMaxDynamicSharedMemorySize, VIN_SMEM);
    cudaFuncSetAttribute(recur_kernel,
                         cudaFuncAttributeMaxDynamicSharedMemorySize, REC_SMEM);

    vin_gemm_kernel<<<dim3(Bn*Tn/128, Hn/128), 256, VIN_SMEM>>>(x, W_in, b_in);
    recur_kernel<<<dim3(8, Bn/4), 512, REC_SMEM>>>(init_state, W_hid, b_hid,
                                                   alpha, out);
}